// round 1
// baseline (speedup 1.0000x reference)
#include <cuda_runtime.h>

#define TW 32                 // tile width  (output)
#define TH 64                 // tile height (output)
#define HALO 5
#define RW (TW + 2*HALO)      // 42 raw cols
#define RH (TH + 2*HALO)      // 74 raw rows
#define NT 256
#define IMG 512
#define PLANE (IMG*IMG)

#define SSIM_C1 0.0001f       // 0.01^2
#define SSIM_C2 0.0009f       // 0.03^2

// Dynamic smem layout:
//   float2 raw[RH*RW]              : 74*42*8   = 24864 B
//   float  hb[5][RH*TW]            : 5*74*32*4 = 47360 B
#define HB_STRIDE (RH*TW)     // 2368 floats per quantity plane
#define SMEM_BYTES (RH*RW*8 + 5*HB_STRIDE*4)   // 72224

__global__ void __launch_bounds__(NT, 3)
ssim_kernel(const float* __restrict__ x, const float* __restrict__ y,
            float* __restrict__ out)
{
    // 11-tap gaussian, sigma = 1.5, normalized (canonical SSIM window values)
    constexpr float W[11] = {
        0.00102838f, 0.00759876f, 0.03600077f, 0.10936078f, 0.21300553f,
        0.26601171f,
        0.21300553f, 0.10936078f, 0.03600077f, 0.00759876f, 0.00102838f
    };

    extern __shared__ float smem[];
    float2* raw = (float2*)smem;            // RH*RW float2
    float*  hb  = smem + RH*RW*2;           // 5 * HB_STRIDE floats

    const int tid   = threadIdx.x;
    const int bx    = blockIdx.x;           // 0..15
    const int by    = blockIdx.y;           // 0..7
    const int plane = blockIdx.z;           // 0..B*C-1

    const float* __restrict__ xp = x + (size_t)plane * PLANE;
    const float* __restrict__ yp = y + (size_t)plane * PLANE;

    const int gx0 = bx * TW - HALO;
    const int gy0 = by * TH - HALO;

    // ---------------- Stage 1: gmem -> smem raw tile (zero-padded) -------
    #pragma unroll 4
    for (int i = tid; i < RH*RW; i += NT) {
        int r = i / RW;
        int c = i - r * RW;
        int gr = gy0 + r;
        int gc = gx0 + c;
        float xv = 0.f, yv = 0.f;
        if ((unsigned)gr < (unsigned)IMG && (unsigned)gc < (unsigned)IMG) {
            int off = gr * IMG + gc;
            xv = xp[off];
            yv = yp[off];
        }
        raw[i] = make_float2(xv, yv);
    }
    __syncthreads();

    // ---------------- Stage 2: horizontal 11-tap, 4-col register block ---
    // tasks: RH rows * 8 groups of 4 cols = 592
    for (int t = tid; t < RH*(TW/4); t += NT) {
        int row = t >> 3;
        int g   = (t & 7) * 4;
        const float2* rp = raw + row * RW + g;

        float a0[4] = {0.f,0.f,0.f,0.f};
        float a1[4] = {0.f,0.f,0.f,0.f};
        float a2[4] = {0.f,0.f,0.f,0.f};
        float a3[4] = {0.f,0.f,0.f,0.f};
        float a4[4] = {0.f,0.f,0.f,0.f};

        #pragma unroll
        for (int p = 0; p < 14; ++p) {
            float2 v  = rp[p];
            float  xx = v.x * v.x;
            float  yy = v.y * v.y;
            float  xy = v.x * v.y;
            #pragma unroll
            for (int i2 = 0; i2 < 4; ++i2) {
                int k = p - i2;
                if (k >= 0 && k <= 10) {
                    a0[i2] = fmaf(v.x, W[k], a0[i2]);
                    a1[i2] = fmaf(v.y, W[k], a1[i2]);
                    a2[i2] = fmaf(xx,  W[k], a2[i2]);
                    a3[i2] = fmaf(yy,  W[k], a3[i2]);
                    a4[i2] = fmaf(xy,  W[k], a4[i2]);
                }
            }
        }

        float* h = hb + row * TW + g;
        #pragma unroll
        for (int i2 = 0; i2 < 4; ++i2) {
            h[i2 + 0*HB_STRIDE] = a0[i2];
            h[i2 + 1*HB_STRIDE] = a1[i2];
            h[i2 + 2*HB_STRIDE] = a2[i2];
            h[i2 + 3*HB_STRIDE] = a3[i2];
            h[i2 + 4*HB_STRIDE] = a4[i2];
        }
    }
    __syncthreads();

    // ---------------- Stage 3: vertical 11-tap, 8-row register block -----
    {
        const int col = tid & 31;
        const int seg = tid >> 5;       // 0..7
        const int r0  = seg * 8;        // base h-row for this segment

        float b0[8], b1[8], b2[8], b3[8], b4[8];
        #pragma unroll
        for (int i2 = 0; i2 < 8; ++i2) {
            b0[i2] = 0.f; b1[i2] = 0.f; b2[i2] = 0.f; b3[i2] = 0.f; b4[i2] = 0.f;
        }

        #pragma unroll
        for (int p = 0; p < 18; ++p) {
            const float* h = hb + (r0 + p) * TW + col;
            float h0 = h[0*HB_STRIDE];
            float h1 = h[1*HB_STRIDE];
            float h2 = h[2*HB_STRIDE];
            float h3 = h[3*HB_STRIDE];
            float h4 = h[4*HB_STRIDE];
            #pragma unroll
            for (int i2 = 0; i2 < 8; ++i2) {
                int k = p - i2;
                if (k >= 0 && k <= 10) {
                    b0[i2] = fmaf(h0, W[k], b0[i2]);
                    b1[i2] = fmaf(h1, W[k], b1[i2]);
                    b2[i2] = fmaf(h2, W[k], b2[i2]);
                    b3[i2] = fmaf(h3, W[k], b3[i2]);
                    b4[i2] = fmaf(h4, W[k], b4[i2]);
                }
            }
        }

        float* op = out + (size_t)plane * PLANE
                        + (size_t)(by * TH + r0) * IMG
                        + bx * TW + col;

        #pragma unroll
        for (int i2 = 0; i2 < 8; ++i2) {
            float mu1    = b0[i2];
            float mu2    = b1[i2];
            float mu1mu2 = mu1 * mu2;
            float mu1sq  = mu1 * mu1;
            float mu2sq  = mu2 * mu2;
            float s11    = b2[i2] - mu1sq;
            float s22    = b3[i2] - mu2sq;
            float s12    = b4[i2] - mu1mu2;
            float num = fmaf(2.f, mu1mu2, SSIM_C1) * fmaf(2.f, s12, SSIM_C2);
            float den = (mu1sq + mu2sq + SSIM_C1) * (s11 + s22 + SSIM_C2);
            op[(size_t)i2 * IMG] = __fdividef(num, den);
        }
    }
}

extern "C" void kernel_launch(void* const* d_in, const int* in_sizes, int n_in,
                              void* d_out, int out_size)
{
    const float* x = (const float*)d_in[0];   // img_out  [B,C,512,512] f32
    const float* y = (const float*)d_in[1];   // img_target
    float* out = (float*)d_out;

    // window_size input (d_in[2]) is fixed at 11; hardcoded weights.
    int planes = in_sizes[0] / PLANE;         // B*C = 48

    cudaFuncSetAttribute(ssim_kernel,
                         cudaFuncAttributeMaxDynamicSharedMemorySize,
                         SMEM_BYTES);

    dim3 grid(IMG / TW, IMG / TH, planes);    // (16, 8, 48)
    ssim_kernel<<<grid, NT, SMEM_BYTES>>>(x, y, out);
}